// round 1
// baseline (speedup 1.0000x reference)
#include <cuda_runtime.h>

#define NB 4096
#define INF 1024
#define OUTF 1024
#define NH 16
#define NM 4096
#define ND 64

// Scratch (device globals: allocation-free rule)
__device__ float g_q[NB * OUTF];
__device__ float g_qn[NB * OUTF];
__device__ float g_mn[NH * NM * ND];

// ---------------------------------------------------------------------------
// GEMM: q = x @ W^T   (X [4096,1024] row-major, W [1024,1024] row-major [out,in])
// 128x128 tile, BK=16, 256 threads, 8x8 per thread.
// ---------------------------------------------------------------------------
__global__ __launch_bounds__(256) void qgemm_kernel(const float* __restrict__ X,
                                                    const float* __restrict__ W,
                                                    float* __restrict__ Q) {
    __shared__ float As[16][128];
    __shared__ float Bs[16][128];
    int tid = threadIdx.x;
    int tx = tid & 15, ty = tid >> 4;
    int m0 = blockIdx.y * 128, n0 = blockIdx.x * 128;

    float acc[8][8];
#pragma unroll
    for (int i = 0; i < 8; i++)
#pragma unroll
        for (int j = 0; j < 8; j++) acc[i][j] = 0.f;

    int lrow = tid >> 1;          // 0..127
    int lk = (tid & 1) * 8;       // 0 or 8
    const float* xg = X + (size_t)(m0 + lrow) * INF + lk;
    const float* wg = W + (size_t)(n0 + lrow) * INF + lk;

    for (int k0 = 0; k0 < INF; k0 += 16) {
        float4 a0 = *(const float4*)(xg + k0);
        float4 a1 = *(const float4*)(xg + k0 + 4);
        float4 b0 = *(const float4*)(wg + k0);
        float4 b1 = *(const float4*)(wg + k0 + 4);
        __syncthreads();  // previous iteration's readers done
        As[lk + 0][lrow] = a0.x; As[lk + 1][lrow] = a0.y;
        As[lk + 2][lrow] = a0.z; As[lk + 3][lrow] = a0.w;
        As[lk + 4][lrow] = a1.x; As[lk + 5][lrow] = a1.y;
        As[lk + 6][lrow] = a1.z; As[lk + 7][lrow] = a1.w;
        Bs[lk + 0][lrow] = b0.x; Bs[lk + 1][lrow] = b0.y;
        Bs[lk + 2][lrow] = b0.z; Bs[lk + 3][lrow] = b0.w;
        Bs[lk + 4][lrow] = b1.x; Bs[lk + 5][lrow] = b1.y;
        Bs[lk + 6][lrow] = b1.z; Bs[lk + 7][lrow] = b1.w;
        __syncthreads();
#pragma unroll
        for (int k = 0; k < 16; k++) {
            float a[8], b[8];
            *(float4*)(a) = *(const float4*)(&As[k][ty * 8]);
            *(float4*)(a + 4) = *(const float4*)(&As[k][ty * 8 + 4]);
            *(float4*)(b) = *(const float4*)(&Bs[k][tx * 8]);
            *(float4*)(b + 4) = *(const float4*)(&Bs[k][tx * 8 + 4]);
#pragma unroll
            for (int i = 0; i < 8; i++)
#pragma unroll
                for (int j = 0; j < 8; j++)
                    acc[i][j] = fmaf(a[i], b[j], acc[i][j]);
        }
    }

#pragma unroll
    for (int i = 0; i < 8; i++) {
        float4 v0 = make_float4(acc[i][0], acc[i][1], acc[i][2], acc[i][3]);
        float4 v1 = make_float4(acc[i][4], acc[i][5], acc[i][6], acc[i][7]);
        float* op = Q + (size_t)(m0 + ty * 8 + i) * OUTF + n0 + tx * 8;
        *(float4*)(op) = v0;
        *(float4*)(op + 4) = v1;
    }
}

// ---------------------------------------------------------------------------
// Row L2-normalize, rows of length 64. One warp per row.
// ---------------------------------------------------------------------------
__global__ __launch_bounds__(256) void rownorm64_kernel(const float* __restrict__ src,
                                                        float* __restrict__ dst) {
    int row = blockIdx.x * 8 + (threadIdx.x >> 5);
    int lane = threadIdx.x & 31;
    const float* p = src + (size_t)row * 64 + lane * 2;
    float2 v = *(const float2*)p;
    float ss = fmaf(v.x, v.x, v.y * v.y);
#pragma unroll
    for (int o = 16; o > 0; o >>= 1) ss += __shfl_xor_sync(0xffffffffu, ss, o);
    float r = rsqrtf(ss);
    float2 w;
    w.x = v.x * r;
    w.y = v.y * r;
    *(float2*)(dst + (size_t)row * 64 + lane * 2) = w;
}

// ---------------------------------------------------------------------------
// exp(x) for x in [-1,1]: degree-7 Taylor (FMA pipe, avoids MUFU bottleneck)
// rel err <= ~7e-5 on [-1,1].
// ---------------------------------------------------------------------------
__device__ __forceinline__ float exp_poly(float x) {
    float p = fmaf(x, 1.9841270e-4f, 1.3888889e-3f);
    p = fmaf(p, x, 8.3333333e-3f);
    p = fmaf(p, x, 4.1666667e-2f);
    p = fmaf(p, x, 1.6666667e-1f);
    p = fmaf(p, x, 0.5f);
    p = fmaf(p, x, 1.0f);
    p = fmaf(p, x, 1.0f);
    return p;
}

// ---------------------------------------------------------------------------
// Attention: per block = (head, 64-row q tile). Single-pass softmax (scores
// bounded in [-1,1] so no max subtraction needed).
// ---------------------------------------------------------------------------
#define PT 68   // stride for d-major tiles
#define PN 72   // stride for natural-layout K tile
#define ATTN_SMEM ((64 * PT * 3 + 64 * PN + 64) * 4)

__global__ __launch_bounds__(256, 2) void attn_kernel(const float* __restrict__ Qn,
                                                      const float* __restrict__ Mn,
                                                      float* __restrict__ Out) {
    extern __shared__ float sm[];
    float* Qt = sm;                // [64 d][PT]  (transposed Q tile)
    float* Kt = Qt + 64 * PT;      // [64 d][PT]  (transposed K tile)
    float* Pt = Kt + 64 * PT;      // [64 j][PT]  (P transposed: [j][i])
    float* Kn = Pt + 64 * PT;      // [64 j][PN]  (natural K tile)
    float* rsum = Kn + 64 * PN;    // [64]

    int tid = threadIdx.x;
    int tx = tid & 15, ty = tid >> 4;
    int h = blockIdx.y;
    int q0 = blockIdx.x * 64;

    // Load Q tile transposed: Qt[d][i]
    {
        int row = tid >> 2;        // i: 0..63
        int cg = tid & 3;
        const float* qp = Qn + (size_t)(q0 + row) * OUTF + h * ND;
#pragma unroll
        for (int u = 0; u < 4; u++) {
            int c4 = cg + 4 * u;   // float4 index 0..15 along d
            float4 v = *(const float4*)(qp + c4 * 4);
            Qt[(c4 * 4 + 0) * PT + row] = v.x;
            Qt[(c4 * 4 + 1) * PT + row] = v.y;
            Qt[(c4 * 4 + 2) * PT + row] = v.z;
            Qt[(c4 * 4 + 3) * PT + row] = v.w;
        }
    }
    if (tid < 64) rsum[tid] = 0.f;

    float o[4][4];
#pragma unroll
    for (int r = 0; r < 4; r++)
#pragma unroll
        for (int c = 0; c < 4; c++) o[r][c] = 0.f;

    const float* mh = Mn + (size_t)h * NM * ND;

    for (int m0 = 0; m0 < NM; m0 += 64) {
        __syncthreads();  // protect Kt/Kn/Pt reuse (prev iter O-GEMM done)
        // Load K tile: both d-major (Kt) and natural (Kn)
        {
            int row = tid >> 2;    // j
            int cg = tid & 3;
            const float* kp = mh + (size_t)(m0 + row) * ND;
#pragma unroll
            for (int u = 0; u < 4; u++) {
                int c4 = cg + 4 * u;
                float4 v = *(const float4*)(kp + c4 * 4);
                *(float4*)(Kn + row * PN + c4 * 4) = v;
                Kt[(c4 * 4 + 0) * PT + row] = v.x;
                Kt[(c4 * 4 + 1) * PT + row] = v.y;
                Kt[(c4 * 4 + 2) * PT + row] = v.z;
                Kt[(c4 * 4 + 3) * PT + row] = v.w;
            }
        }
        __syncthreads();

        // S = Q K^T : frag s[r][c], rows i=4ty+r, cols j=4tx+c
        float s[4][4];
#pragma unroll
        for (int r = 0; r < 4; r++)
#pragma unroll
            for (int c = 0; c < 4; c++) s[r][c] = 0.f;

#pragma unroll 8
        for (int d = 0; d < 64; d++) {
            float4 a = *(const float4*)(Qt + d * PT + 4 * ty);
            float4 b = *(const float4*)(Kt + d * PT + 4 * tx);
            float av[4] = {a.x, a.y, a.z, a.w};
            float bv[4] = {b.x, b.y, b.z, b.w};
#pragma unroll
            for (int r = 0; r < 4; r++)
#pragma unroll
                for (int c = 0; c < 4; c++)
                    s[r][c] = fmaf(av[r], bv[c], s[r][c]);
        }

        // exp + per-thread row partial sums
        float rs[4] = {0.f, 0.f, 0.f, 0.f};
#pragma unroll
        for (int r = 0; r < 4; r++)
#pragma unroll
            for (int c = 0; c < 4; c++) {
                float p = exp_poly(s[r][c]);
                s[r][c] = p;
                rs[r] += p;
            }

        // Stage P transposed: Pt[j][i]
#pragma unroll
        for (int c = 0; c < 4; c++) {
            float4 pv = make_float4(s[0][c], s[1][c], s[2][c], s[3][c]);
            *(float4*)(Pt + (4 * tx + c) * PT + 4 * ty) = pv;
        }

        // Reduce row sums across tx (16-lane halves of the warp)
#pragma unroll
        for (int off = 1; off < 16; off <<= 1)
#pragma unroll
            for (int r = 0; r < 4; r++)
                rs[r] += __shfl_xor_sync(0xffffffffu, rs[r], off);
        if (tx == 0) {
#pragma unroll
            for (int r = 0; r < 4; r++) rsum[4 * ty + r] += rs[r];
        }
        __syncthreads();

        // O += P V : O[i][dd], i=4ty+r, dd=4tx+c
#pragma unroll 8
        for (int j = 0; j < 64; j++) {
            float4 p = *(const float4*)(Pt + j * PT + 4 * ty);
            float4 v = *(const float4*)(Kn + j * PN + 4 * tx);
            float pv[4] = {p.x, p.y, p.z, p.w};
            float vv[4] = {v.x, v.y, v.z, v.w};
#pragma unroll
            for (int r = 0; r < 4; r++)
#pragma unroll
                for (int c = 0; c < 4; c++)
                    o[r][c] = fmaf(pv[r], vv[c], o[r][c]);
        }
    }
    __syncthreads();

    // Epilogue: out = O * sqrt(64) / rowsum
#pragma unroll
    for (int r = 0; r < 4; r++) {
        float inv = 8.0f / rsum[4 * ty + r];
        float4 w = make_float4(o[r][0] * inv, o[r][1] * inv,
                               o[r][2] * inv, o[r][3] * inv);
        *(float4*)(Out + (size_t)(q0 + 4 * ty + r) * OUTF + h * ND + 4 * tx) = w;
    }
}

// ---------------------------------------------------------------------------
extern "C" void kernel_launch(void* const* d_in, const int* in_sizes, int n_in,
                              void* d_out, int out_size) {
    const float* x = (const float*)d_in[0];
    const float* W = (const float*)d_in[1];
    const float* mem = (const float*)d_in[2];
    float* out = (float*)d_out;

    float *q, *qn, *mn;
    cudaGetSymbolAddress((void**)&q, g_q);
    cudaGetSymbolAddress((void**)&qn, g_qn);
    cudaGetSymbolAddress((void**)&mn, g_mn);

    cudaFuncSetAttribute(attn_kernel, cudaFuncAttributeMaxDynamicSharedMemorySize,
                         ATTN_SMEM);

    qgemm_kernel<<<dim3(OUTF / 128, NB / 128), 256>>>(x, W, q);
    rownorm64_kernel<<<(NB * NH) / 8, 256>>>(q, qn);
    rownorm64_kernel<<<(NH * NM) / 8, 256>>>(mem, mn);
    attn_kernel<<<dim3(NB / 64, NH), 256, ATTN_SMEM>>>(qn, mn, out);
}

// round 3
// speedup vs baseline: 5.8417x; 5.8417x over previous
#include <cuda_runtime.h>
#include <cstdint>

#define NB 4096
#define INF 1024
#define OUTF 1024
#define NH 16
#define NM 4096
#define ND 64

// Scratch (device globals: allocation-free rule)
__device__ float g_q[NB * OUTF];
__device__ float g_qn[NB * OUTF];
__device__ float g_mn[NH * NM * ND];

// ===========================================================================
// helpers
// ===========================================================================
__device__ __forceinline__ uint32_t smem_u32(const void* p) {
    uint32_t a;
    asm("{ .reg .u64 t; cvta.to.shared.u64 t, %1; cvt.u32.u64 %0, t; }"
        : "=r"(a) : "l"(p));
    return a;
}
__device__ __forceinline__ uint32_t f2tf32(float f) {
    uint32_t u;
    asm("cvt.rna.tf32.f32 %0, %1;" : "=r"(u) : "f"(f));
    return u;
}
__device__ __forceinline__ void mma_tf32(float* d, const uint32_t* a,
                                         uint32_t b0, uint32_t b1) {
    asm volatile(
        "mma.sync.aligned.m16n8k8.row.col.f32.tf32.tf32.f32 "
        "{%0,%1,%2,%3},{%4,%5,%6,%7},{%8,%9},{%0,%1,%2,%3};"
        : "+f"(d[0]), "+f"(d[1]), "+f"(d[2]), "+f"(d[3])
        : "r"(a[0]), "r"(a[1]), "r"(a[2]), "r"(a[3]), "r"(b0), "r"(b1));
}
__device__ __forceinline__ void cpasync16(uint32_t dst, const void* src) {
    asm volatile("cp.async.cg.shared.global [%0], [%1], 16;"
                 :: "r"(dst), "l"(src) : "memory");
}
__device__ __forceinline__ void cp_commit() {
    asm volatile("cp.async.commit_group;" ::: "memory");
}

// ===========================================================================
// q-GEMM: q = x @ W^T via mma.sync tf32. 128x128 tile, BK=16, 256 thr, 8 warps
// warp tile 32(M) x 64(N). Double-buffered smem, cvt.rna staging.
// ===========================================================================
#define QG_STR 20

__global__ __launch_bounds__(256, 2) void qgemm_mma(const float* __restrict__ X,
                                                    const float* __restrict__ W,
                                                    float* __restrict__ Q) {
    __shared__ float Xs[2][128 * QG_STR];
    __shared__ float Ws[2][128 * QG_STR];

    int tid = threadIdx.x;
    int lane = tid & 31, w = tid >> 5;
    int g = lane >> 2, la3 = lane & 3;
    int wm = (w & 3) * 32;   // warp row offset in 128 tile
    int wn = (w >> 2) * 64;  // warp col offset
    int m0 = blockIdx.y * 128, n0 = blockIdx.x * 128;

    int srow = tid >> 1;            // 0..127
    int scol = (tid & 1) * 8;       // 0 or 8
    const float* xg = X + (size_t)(m0 + srow) * INF + scol;
    const float* wg = W + (size_t)(n0 + srow) * INF + scol;

    float acc[2][8][4];
#pragma unroll
    for (int mt = 0; mt < 2; mt++)
#pragma unroll
        for (int nt = 0; nt < 8; nt++)
#pragma unroll
            for (int e = 0; e < 4; e++) acc[mt][nt][e] = 0.f;

    // stage k0=0 into buf 0
    {
        float4 a0 = *(const float4*)(xg);
        float4 a1 = *(const float4*)(xg + 4);
        float4 b0 = *(const float4*)(wg);
        float4 b1 = *(const float4*)(wg + 4);
        float* xd = &Xs[0][srow * QG_STR + scol];
        float* wd = &Ws[0][srow * QG_STR + scol];
        xd[0] = __uint_as_float(f2tf32(a0.x)); xd[1] = __uint_as_float(f2tf32(a0.y));
        xd[2] = __uint_as_float(f2tf32(a0.z)); xd[3] = __uint_as_float(f2tf32(a0.w));
        xd[4] = __uint_as_float(f2tf32(a1.x)); xd[5] = __uint_as_float(f2tf32(a1.y));
        xd[6] = __uint_as_float(f2tf32(a1.z)); xd[7] = __uint_as_float(f2tf32(a1.w));
        wd[0] = __uint_as_float(f2tf32(b0.x)); wd[1] = __uint_as_float(f2tf32(b0.y));
        wd[2] = __uint_as_float(f2tf32(b0.z)); wd[3] = __uint_as_float(f2tf32(b0.w));
        wd[4] = __uint_as_float(f2tf32(b1.x)); wd[5] = __uint_as_float(f2tf32(b1.y));
        wd[6] = __uint_as_float(f2tf32(b1.z)); wd[7] = __uint_as_float(f2tf32(b1.w));
    }
    __syncthreads();

    for (int k0 = 0; k0 < INF; k0 += 16) {
        int buf = (k0 >> 4) & 1;
        bool more = (k0 + 16 < INF);
        float4 a0, a1, b0, b1;
        if (more) {
            a0 = *(const float4*)(xg + k0 + 16);
            a1 = *(const float4*)(xg + k0 + 20);
            b0 = *(const float4*)(wg + k0 + 16);
            b1 = *(const float4*)(wg + k0 + 20);
        }
        // compute on buf
#pragma unroll
        for (int s = 0; s < 2; s++) {
            uint32_t af[2][4];
#pragma unroll
            for (int mt = 0; mt < 2; mt++) {
                int rr = wm + mt * 16 + g;
                af[mt][0] = __float_as_uint(Xs[buf][rr * QG_STR + 8 * s + la3]);
                af[mt][1] = __float_as_uint(Xs[buf][(rr + 8) * QG_STR + 8 * s + la3]);
                af[mt][2] = __float_as_uint(Xs[buf][rr * QG_STR + 8 * s + la3 + 4]);
                af[mt][3] = __float_as_uint(Xs[buf][(rr + 8) * QG_STR + 8 * s + la3 + 4]);
            }
#pragma unroll
            for (int nt = 0; nt < 8; nt++) {
                int nr = wn + nt * 8 + g;
                uint32_t bb0 = __float_as_uint(Ws[buf][nr * QG_STR + 8 * s + la3]);
                uint32_t bb1 = __float_as_uint(Ws[buf][nr * QG_STR + 8 * s + la3 + 4]);
                mma_tf32(acc[0][nt], af[0], bb0, bb1);
                mma_tf32(acc[1][nt], af[1], bb0, bb1);
            }
        }
        if (more) {
            float* xd = &Xs[buf ^ 1][srow * QG_STR + scol];
            float* wd = &Ws[buf ^ 1][srow * QG_STR + scol];
            xd[0] = __uint_as_float(f2tf32(a0.x)); xd[1] = __uint_as_float(f2tf32(a0.y));
            xd[2] = __uint_as_float(f2tf32(a0.z)); xd[3] = __uint_as_float(f2tf32(a0.w));
            xd[4] = __uint_as_float(f2tf32(a1.x)); xd[5] = __uint_as_float(f2tf32(a1.y));
            xd[6] = __uint_as_float(f2tf32(a1.z)); xd[7] = __uint_as_float(f2tf32(a1.w));
            wd[0] = __uint_as_float(f2tf32(b0.x)); wd[1] = __uint_as_float(f2tf32(b0.y));
            wd[2] = __uint_as_float(f2tf32(b0.z)); wd[3] = __uint_as_float(f2tf32(b0.w));
            wd[4] = __uint_as_float(f2tf32(b1.x)); wd[5] = __uint_as_float(f2tf32(b1.y));
            wd[6] = __uint_as_float(f2tf32(b1.z)); wd[7] = __uint_as_float(f2tf32(b1.w));
        }
        __syncthreads();
    }

    // epilogue
#pragma unroll
    for (int mt = 0; mt < 2; mt++)
#pragma unroll
        for (int nt = 0; nt < 8; nt++) {
            int rlo = m0 + wm + mt * 16 + g;
            int col = n0 + wn + nt * 8 + 2 * la3;
            float2 lo = make_float2(acc[mt][nt][0], acc[mt][nt][1]);
            float2 hi = make_float2(acc[mt][nt][2], acc[mt][nt][3]);
            *(float2*)(Q + (size_t)rlo * OUTF + col) = lo;
            *(float2*)(Q + (size_t)(rlo + 8) * OUTF + col) = hi;
        }
}

// ===========================================================================
// Row L2-normalize, 64-elem rows, warp per row
// ===========================================================================
__global__ __launch_bounds__(256) void rownorm64_kernel(const float* __restrict__ src,
                                                        float* __restrict__ dst) {
    int row = blockIdx.x * 8 + (threadIdx.x >> 5);
    int lane = threadIdx.x & 31;
    const float* p = src + (size_t)row * 64 + lane * 2;
    float2 v = *(const float2*)p;
    float ss = fmaf(v.x, v.x, v.y * v.y);
#pragma unroll
    for (int o = 16; o > 0; o >>= 1) ss += __shfl_xor_sync(0xffffffffu, ss, o);
    float r = rsqrtf(ss);
    float2 w;
    w.x = v.x * r;
    w.y = v.y * r;
    *(float2*)(dst + (size_t)row * 64 + lane * 2) = w;
}

// ===========================================================================
// Attention via mma.sync tf32. CTA = (head, 256 q rows), 8 warps x 32 rows.
// KV tile 64 rows, cp.async double-buffered. Single-pass softmax.
// smem (floats): Kb[2][64*68] | PQ[256*68] (Q staging, then per-warp P)
// ===========================================================================
#define STRIDE 68
#define KT 64
#define KB_W (KT * STRIDE)
#define SM_PQ (2 * KB_W)
#define AT_SMEM_BYTES ((2 * KB_W + 256 * STRIDE) * 4)

__global__ __launch_bounds__(256, 1) void attn_mma(const float* __restrict__ Qn,
                                                   const float* __restrict__ Mn,
                                                   float* __restrict__ Out) {
    extern __shared__ float sm[];
    uint32_t smb = smem_u32(sm);

    int tid = threadIdx.x;
    int lane = tid & 31, w = tid >> 5;
    int g = lane >> 2, la3 = lane & 3;
    int h = blockIdx.y;
    int q0 = blockIdx.x * 256;
    const float* mh = Mn + (size_t)h * NM * ND;

    // ---- Stage Q tile (tf32-rounded) into PQ region ----
    {
        int row = tid >> 1;
        int c0 = (tid & 1) * 32;
#pragma unroll
        for (int hf = 0; hf < 2; hf++) {
            int r = row + hf * 128;
            const float* qp = Qn + (size_t)(q0 + r) * OUTF + h * ND + c0;
            float* dst = sm + SM_PQ + r * STRIDE + c0;
#pragma unroll
            for (int u = 0; u < 8; u++) {
                float4 v = *(const float4*)(qp + 4 * u);
                float4 t;
                t.x = __uint_as_float(f2tf32(v.x));
                t.y = __uint_as_float(f2tf32(v.y));
                t.z = __uint_as_float(f2tf32(v.z));
                t.w = __uint_as_float(f2tf32(v.w));
                *(float4*)(dst + 4 * u) = t;
            }
        }
    }
    __syncthreads();

    // ---- Load persistent Q a-frags ----
    int wr = w * 32;
    uint32_t qf[2][8][4];
#pragma unroll
    for (int mt = 0; mt < 2; mt++)
#pragma unroll
        for (int s = 0; s < 8; s++) {
            int rr = wr + mt * 16 + g;
            const float* base = sm + SM_PQ;
            qf[mt][s][0] = __float_as_uint(base[rr * STRIDE + 8 * s + la3]);
            qf[mt][s][1] = __float_as_uint(base[(rr + 8) * STRIDE + 8 * s + la3]);
            qf[mt][s][2] = __float_as_uint(base[rr * STRIDE + 8 * s + la3 + 4]);
            qf[mt][s][3] = __float_as_uint(base[(rr + 8) * STRIDE + 8 * s + la3 + 4]);
        }
    __syncthreads();   // everyone done reading Q before P overwrites region

    float oacc[2][8][4];
#pragma unroll
    for (int mt = 0; mt < 2; mt++)
#pragma unroll
        for (int nt = 0; nt < 8; nt++)
#pragma unroll
            for (int e = 0; e < 4; e++) oacc[mt][nt][e] = 0.f;
    float psum[2][2] = {{0.f, 0.f}, {0.f, 0.f}};

    // prefetch tile 0
    {
        const float* src = mh;
#pragma unroll
        for (int u = 0; u < 4; u++) {
            int chunk = tid + 256 * u;
            int r = chunk >> 4, c = (chunk & 15) << 2;
            cpasync16(smb + (uint32_t)(r * STRIDE + c) * 4, src + r * ND + c);
        }
        cp_commit();
    }

    float* Pw = sm + SM_PQ + wr * STRIDE;

    for (int t = 0; t < 64; t++) {
        int b = t & 1;
        __syncthreads();  // prev iter done reading Kb[b^1] before its refill
        if (t < 63) {
            const float* src = mh + (size_t)(t + 1) * KT * ND;
            uint32_t dbase = smb + (uint32_t)((b ^ 1) * KB_W) * 4;
#pragma unroll
            for (int u = 0; u < 4; u++) {
                int chunk = tid + 256 * u;
                int r = chunk >> 4, c = (chunk & 15) << 2;
                cpasync16(dbase + (uint32_t)(r * STRIDE + c) * 4, src + r * ND + c);
            }
            cp_commit();
            asm volatile("cp.async.wait_group 1;" ::: "memory");
        } else {
            asm volatile("cp.async.wait_group 0;" ::: "memory");
        }
        __syncthreads();

        const float* Kb = sm + b * KB_W;

        // ---- GEMM1: S = Q K^T ----
        float sacc[2][8][4];
#pragma unroll
        for (int mt = 0; mt < 2; mt++)
#pragma unroll
            for (int nt = 0; nt < 8; nt++)
#pragma unroll
                for (int e = 0; e < 4; e++) sacc[mt][nt][e] = 0.f;

#pragma unroll
        for (int s = 0; s < 8; s++) {
#pragma unroll
            for (int nt = 0; nt < 8; nt++) {
                uint32_t b0 = __float_as_uint(Kb[(8 * nt + g) * STRIDE + 8 * s + la3]);
                uint32_t b1 = __float_as_uint(Kb[(8 * nt + g) * STRIDE + 8 * s + la3 + 4]);
                mma_tf32(sacc[0][nt], qf[0][s], b0, b1);
                mma_tf32(sacc[1][nt], qf[1][s], b0, b1);
            }
        }

        // ---- exp + row-sum + store P (tf32) ----
#pragma unroll
        for (int mt = 0; mt < 2; mt++) {
#pragma unroll
            for (int nt = 0; nt < 8; nt++) {
                float e0 = __expf(sacc[mt][nt][0]);
                float e1 = __expf(sacc[mt][nt][1]);
                float e2 = __expf(sacc[mt][nt][2]);
                float e3 = __expf(sacc[mt][nt][3]);
                psum[mt][0] += e0 + e1;
                psum[mt][1] += e2 + e3;
                float2 lo = make_float2(__uint_as_float(f2tf32(e0)),
                                        __uint_as_float(f2tf32(e1)));
                float2 hi = make_float2(__uint_as_float(f2tf32(e2)),
                                        __uint_as_float(f2tf32(e3)));
                int rr = mt * 16 + g;
                *(float2*)(Pw + rr * STRIDE + 8 * nt + 2 * la3) = lo;
                *(float2*)(Pw + (rr + 8) * STRIDE + 8 * nt + 2 * la3) = hi;
            }
        }
        __syncwarp();

        // ---- GEMM2: O += P V ----
#pragma unroll
        for (int s2 = 0; s2 < 8; s2++) {
            uint32_t a[2][4];
#pragma unroll
            for (int mt = 0; mt < 2; mt++) {
                int rr = mt * 16 + g;
                a[mt][0] = __float_as_uint(Pw[rr * STRIDE + 8 * s2 + la3]);
                a[mt][1] = __float_as_uint(Pw[(rr + 8) * STRIDE + 8 * s2 + la3]);
                a[mt][2] = __float_as_uint(Pw[rr * STRIDE + 8 * s2 + la3 + 4]);
                a[mt][3] = __float_as_uint(Pw[(rr + 8) * STRIDE + 8 * s2 + la3 + 4]);
            }
#pragma unroll
            for (int nt = 0; nt < 8; nt++) {
                uint32_t b0 = __float_as_uint(Kb[(8 * s2 + la3) * STRIDE + 8 * nt + g]);
                uint32_t b1 = __float_as_uint(Kb[(8 * s2 + la3 + 4) * STRIDE + 8 * nt + g]);
                mma_tf32(oacc[0][nt], a[0], b0, b1);
                mma_tf32(oacc[1][nt], a[1], b0, b1);
            }
        }
        __syncwarp();  // P reads done before next iter's P writes
    }

    // ---- Epilogue: scale by sqrt(64)/rowsum, write out ----
#pragma unroll
    for (int mt = 0; mt < 2; mt++) {
        float s0 = psum[mt][0], s1 = psum[mt][1];
        s0 += __shfl_xor_sync(0xffffffffu, s0, 1);
        s0 += __shfl_xor_sync(0xffffffffu, s0, 2);
        s1 += __shfl_xor_sync(0xffffffffu, s1, 1);
        s1 += __shfl_xor_sync(0xffffffffu, s1, 2);
        float sc0 = 8.0f / s0;
        float sc1 = 8.0f / s1;
        int rlo = q0 + wr + mt * 16 + g;
#pragma unroll
        for (int nt = 0; nt < 8; nt++) {
            int col = h * ND + 8 * nt + 2 * la3;
            float2 lo = make_float2(oacc[mt][nt][0] * sc0, oacc[mt][nt][1] * sc0);
            float2 hi = make_float2(oacc[mt][nt][2] * sc1, oacc[mt][nt][3] * sc1);
            *(float2*)(Out + (size_t)rlo * OUTF + col) = lo;
            *(float2*)(Out + (size_t)(rlo + 8) * OUTF + col) = hi;
        }
    }
}

// ===========================================================================
extern "C" void kernel_launch(void* const* d_in, const int* in_sizes, int n_in,
                              void* d_out, int out_size) {
    const float* x = (const float*)d_in[0];
    const float* W = (const float*)d_in[1];
    const float* mem = (const float*)d_in[2];
    float* out = (float*)d_out;

    float *q, *qn, *mn;
    cudaGetSymbolAddress((void**)&q, g_q);
    cudaGetSymbolAddress((void**)&qn, g_qn);
    cudaGetSymbolAddress((void**)&mn, g_mn);

    cudaFuncSetAttribute(attn_mma, cudaFuncAttributeMaxDynamicSharedMemorySize,
                         AT_SMEM_BYTES);

    qgemm_mma<<<dim3(OUTF / 128, NB / 128), 256>>>(x, W, q);
    rownorm64_kernel<<<(NB * NH) / 8, 256>>>(q, qn);
    rownorm64_kernel<<<(NH * NM) / 8, 256>>>(mem, mn);
    attn_mma<<<dim3(NB / 256, NH), 256, AT_SMEM_BYTES>>>(qn, mn, out);
}

// round 4
// speedup vs baseline: 6.4121x; 1.0977x over previous
#include <cuda_runtime.h>
#include <cstdint>

#define NB 4096
#define INF 1024
#define OUTF 1024
#define NH 16
#define NM 4096
#define ND 64

// Scratch (device globals: allocation-free rule)
__device__ float g_qn[NB * OUTF];
__device__ float g_mn[NH * NM * ND];

// ===========================================================================
// helpers
// ===========================================================================
__device__ __forceinline__ uint32_t smem_u32(const void* p) {
    uint32_t a;
    asm("{ .reg .u64 t; cvta.to.shared.u64 t, %1; cvt.u32.u64 %0, t; }"
        : "=r"(a) : "l"(p));
    return a;
}
__device__ __forceinline__ uint32_t f2tf32(float f) {
    uint32_t u;
    asm("cvt.rna.tf32.f32 %0, %1;" : "=r"(u) : "f"(f));
    return u;
}
__device__ __forceinline__ float f2tf32f(float f) {
    return __uint_as_float(f2tf32(f));
}
__device__ __forceinline__ void mma_tf32(float* d, const uint32_t* a,
                                         uint32_t b0, uint32_t b1) {
    asm volatile(
        "mma.sync.aligned.m16n8k8.row.col.f32.tf32.tf32.f32 "
        "{%0,%1,%2,%3},{%4,%5,%6,%7},{%8,%9},{%0,%1,%2,%3};"
        : "+f"(d[0]), "+f"(d[1]), "+f"(d[2]), "+f"(d[3])
        : "r"(a[0]), "r"(a[1]), "r"(a[2]), "r"(a[3]), "r"(b0), "r"(b1));
}
__device__ __forceinline__ void cpasync16(uint32_t dst, const void* src) {
    asm volatile("cp.async.cg.shared.global [%0], [%1], 16;"
                 :: "r"(dst), "l"(src) : "memory");
}
__device__ __forceinline__ void cp_commit() {
    asm volatile("cp.async.commit_group;" ::: "memory");
}
__device__ __forceinline__ void cp_wait1() {
    asm volatile("cp.async.wait_group 1;" ::: "memory");
}
__device__ __forceinline__ void cp_wait0() {
    asm volatile("cp.async.wait_group 0;" ::: "memory");
}

// exp(x), x in ~[-1,1]: degree-7 Taylor on the FMA pipe (MUFU stays idle)
__device__ __forceinline__ float exp_poly(float x) {
    float p = fmaf(x, 1.9841270e-4f, 1.3888889e-3f);
    p = fmaf(p, x, 8.3333333e-3f);
    p = fmaf(p, x, 4.1666667e-2f);
    p = fmaf(p, x, 1.6666667e-1f);
    p = fmaf(p, x, 0.5f);
    p = fmaf(p, x, 1.0f);
    p = fmaf(p, x, 1.0f);
    return p;
}

// ===========================================================================
// q-GEMM: qn = rownorm64(x @ W^T), tf32-rounded output. cp.async 3-stage.
// 128x128 tile, BK=16, 256 thr, warp tile 32x64. Fused per-head L2 norm.
// ===========================================================================
#define QGS 20
#define QG_TILE (128 * QGS)
#define QG_WOFF (3 * QG_TILE)
#define QG_SMEM (6 * QG_TILE * 4)

__global__ __launch_bounds__(256, 2) void qgemm_mma(const float* __restrict__ X,
                                                    const float* __restrict__ W,
                                                    float* __restrict__ Qn) {
    extern __shared__ float qsm[];
    uint32_t smb = smem_u32(qsm);

    int tid = threadIdx.x;
    int lane = tid & 31, w = tid >> 5;
    int g = lane >> 2, la3 = lane & 3;
    int wm = (w & 3) * 32;
    int wn = (w >> 2) * 64;
    int m0 = blockIdx.y * 128, n0 = blockIdx.x * 128;

    float acc[2][8][4];
#pragma unroll
    for (int mt = 0; mt < 2; mt++)
#pragma unroll
        for (int nt = 0; nt < 8; nt++)
#pragma unroll
            for (int e = 0; e < 4; e++) acc[mt][nt][e] = 0.f;

    // staging lambda-ish via macro
#define QG_STAGE(kt, sl)                                                       \
    do {                                                                       \
        _Pragma("unroll")                                                      \
        for (int u = 0; u < 2; u++) {                                          \
            int chunk = tid + 256 * u;                                         \
            int r = chunk >> 2, c4 = (chunk & 3) << 2;                         \
            cpasync16(smb + (uint32_t)((sl) * QG_TILE + r * QGS + c4) * 4,     \
                      X + (size_t)(m0 + r) * INF + (kt) * 16 + c4);            \
            cpasync16(smb + (uint32_t)(QG_WOFF + (sl) * QG_TILE + r * QGS + c4) * 4, \
                      W + (size_t)(n0 + r) * INF + (kt) * 16 + c4);            \
        }                                                                      \
    } while (0)

    QG_STAGE(0, 0); cp_commit();
    QG_STAGE(1, 1); cp_commit();

    for (int kt = 0; kt < 64; kt++) {
        if (kt < 63) cp_wait1(); else cp_wait0();
        __syncthreads();
        if (kt + 2 < 64) { QG_STAGE(kt + 2, (kt + 2) % 3); cp_commit(); }

        const float* Xs = qsm + (kt % 3) * QG_TILE;
        const float* Ws = qsm + QG_WOFF + (kt % 3) * QG_TILE;
#pragma unroll
        for (int s = 0; s < 2; s++) {
            uint32_t af[2][4];
#pragma unroll
            for (int mt = 0; mt < 2; mt++) {
                int rr = wm + mt * 16 + g;
                af[mt][0] = f2tf32(Xs[rr * QGS + 8 * s + la3]);
                af[mt][1] = f2tf32(Xs[(rr + 8) * QGS + 8 * s + la3]);
                af[mt][2] = f2tf32(Xs[rr * QGS + 8 * s + la3 + 4]);
                af[mt][3] = f2tf32(Xs[(rr + 8) * QGS + 8 * s + la3 + 4]);
            }
#pragma unroll
            for (int nt = 0; nt < 8; nt++) {
                int nr = wn + nt * 8 + g;
                uint32_t b0 = f2tf32(Ws[nr * QGS + 8 * s + la3]);
                uint32_t b1 = f2tf32(Ws[nr * QGS + 8 * s + la3 + 4]);
                mma_tf32(acc[0][nt], af[0], b0, b1);
                mma_tf32(acc[1][nt], af[1], b0, b1);
            }
        }
    }

    // fused per-head (64-col) L2 norm epilogue; write tf32-rounded qn
#pragma unroll
    for (int mt = 0; mt < 2; mt++) {
        float sq0 = 0.f, sq1 = 0.f;
#pragma unroll
        for (int nt = 0; nt < 8; nt++) {
            sq0 = fmaf(acc[mt][nt][0], acc[mt][nt][0], sq0);
            sq0 = fmaf(acc[mt][nt][1], acc[mt][nt][1], sq0);
            sq1 = fmaf(acc[mt][nt][2], acc[mt][nt][2], sq1);
            sq1 = fmaf(acc[mt][nt][3], acc[mt][nt][3], sq1);
        }
        sq0 += __shfl_xor_sync(0xffffffffu, sq0, 1);
        sq0 += __shfl_xor_sync(0xffffffffu, sq0, 2);
        sq1 += __shfl_xor_sync(0xffffffffu, sq1, 1);
        sq1 += __shfl_xor_sync(0xffffffffu, sq1, 2);
        float r0 = rsqrtf(sq0), r1 = rsqrtf(sq1);
        int rlo = m0 + wm + mt * 16 + g;
#pragma unroll
        for (int nt = 0; nt < 8; nt++) {
            int col = n0 + wn + nt * 8 + 2 * la3;
            float2 lo = make_float2(f2tf32f(acc[mt][nt][0] * r0),
                                    f2tf32f(acc[mt][nt][1] * r0));
            float2 hi = make_float2(f2tf32f(acc[mt][nt][2] * r1),
                                    f2tf32f(acc[mt][nt][3] * r1));
            *(float2*)(Qn + (size_t)rlo * OUTF + col) = lo;
            *(float2*)(Qn + (size_t)(rlo + 8) * OUTF + col) = hi;
        }
    }
}

// ===========================================================================
// Row L2-normalize memories, 64-elem rows, tf32-rounded output
// ===========================================================================
__global__ __launch_bounds__(256) void rownorm64_kernel(const float* __restrict__ src,
                                                        float* __restrict__ dst) {
    int row = blockIdx.x * 8 + (threadIdx.x >> 5);
    int lane = threadIdx.x & 31;
    const float* p = src + (size_t)row * 64 + lane * 2;
    float2 v = *(const float2*)p;
    float ss = fmaf(v.x, v.x, v.y * v.y);
#pragma unroll
    for (int o = 16; o > 0; o >>= 1) ss += __shfl_xor_sync(0xffffffffu, ss, o);
    float r = rsqrtf(ss);
    float2 w;
    w.x = f2tf32f(v.x * r);
    w.y = f2tf32f(v.y * r);
    *(float2*)(dst + (size_t)row * 64 + lane * 2) = w;
}

// ===========================================================================
// Attention. CTA = (head, 256 q rows), 8 warps x 32 rows. KT=64.
// Dual K copies: stride-68 (GEMM1, row-pattern reads) + stride-72 (GEMM2,
// column-pattern reads; 72 mod 32 = 8 -> conflict-free). 3-stage cp.async.
// exp via FMA-pipe poly, interleaved into the other half's MMAs.
// smem floats: K68[3][64*68] | K72[3][64*72] | PQ[256*68]
// ===========================================================================
#define KT 64
#define K68W (KT * 68)
#define K72W (KT * 72)
#define K72_OFF (3 * K68W)
#define PQ_OFF (3 * K68W + 3 * K72W)
#define AT_SMEM ((3 * K68W + 3 * K72W + 256 * 68) * 4)
#define NTILES (NM / KT)

__global__ __launch_bounds__(256, 1) void attn_mma(const float* __restrict__ Qn,
                                                   const float* __restrict__ Mn,
                                                   float* __restrict__ Out) {
    extern __shared__ float sm[];
    uint32_t smb = smem_u32(sm);

    int tid = threadIdx.x;
    int lane = tid & 31, w = tid >> 5;
    int g = lane >> 2, la3 = lane & 3;
    int h = blockIdx.y;
    int q0 = blockIdx.x * 256;
    const float* mh = Mn + (size_t)h * NM * ND;

#define AT_STAGE(tt, sl)                                                       \
    do {                                                                       \
        const float* src_ = mh + (size_t)(tt) * KT * ND;                       \
        _Pragma("unroll")                                                      \
        for (int u = 0; u < 4; u++) {                                          \
            int chunk = tid + 256 * u;                                         \
            int r = chunk >> 4, c4 = (chunk & 15) << 2;                        \
            const float* s_ = src_ + r * ND + c4;                              \
            cpasync16(smb + (uint32_t)((sl) * K68W + r * 68 + c4) * 4, s_);    \
            cpasync16(smb + (uint32_t)(K72_OFF + (sl) * K72W + r * 72 + c4) * 4, s_); \
        }                                                                      \
    } while (0)

    AT_STAGE(0, 0); cp_commit();
    AT_STAGE(1, 1); cp_commit();

    // ---- Stage Q tile (already tf32) into PQ region ----
    {
        int row = tid >> 1;
        int c0 = (tid & 1) * 32;
#pragma unroll
        for (int hf = 0; hf < 2; hf++) {
            int r = row + hf * 128;
            const float* qp = Qn + (size_t)(q0 + r) * OUTF + h * ND + c0;
            float* dst = sm + PQ_OFF + r * 68 + c0;
#pragma unroll
            for (int u = 0; u < 8; u++) *(float4*)(dst + 4 * u) = *(const float4*)(qp + 4 * u);
        }
    }
    __syncthreads();

    // ---- persistent Q a-frags ----
    int wr = w * 32;
    uint32_t qf[2][8][4];
#pragma unroll
    for (int mt = 0; mt < 2; mt++)
#pragma unroll
        for (int s = 0; s < 8; s++) {
            int rr = wr + mt * 16 + g;
            const float* base = sm + PQ_OFF;
            qf[mt][s][0] = __float_as_uint(base[rr * 68 + 8 * s + la3]);
            qf[mt][s][1] = __float_as_uint(base[(rr + 8) * 68 + 8 * s + la3]);
            qf[mt][s][2] = __float_as_uint(base[rr * 68 + 8 * s + la3 + 4]);
            qf[mt][s][3] = __float_as_uint(base[(rr + 8) * 68 + 8 * s + la3 + 4]);
        }
    __syncthreads();

    float oacc[2][8][4];
#pragma unroll
    for (int mt = 0; mt < 2; mt++)
#pragma unroll
        for (int nt = 0; nt < 8; nt++)
#pragma unroll
            for (int e = 0; e < 4; e++) oacc[mt][nt][e] = 0.f;
    float psum[2][2] = {{0.f, 0.f}, {0.f, 0.f}};

    float* Pw = sm + PQ_OFF + wr * 68;

    // exp one 16x8 block: sa = sacc[mt][nt], write P, accumulate psum[mt]
#define EXP_BLOCK(sa, mt, nt)                                                  \
    do {                                                                       \
        float e0 = exp_poly((sa)[0]);                                          \
        float e1 = exp_poly((sa)[1]);                                          \
        float e2 = exp_poly((sa)[2]);                                          \
        float e3 = exp_poly((sa)[3]);                                          \
        psum[mt][0] += e0 + e1;                                                \
        psum[mt][1] += e2 + e3;                                                \
        float2 lo = make_float2(f2tf32f(e0), f2tf32f(e1));                     \
        float2 hi = make_float2(f2tf32f(e2), f2tf32f(e3));                     \
        *(float2*)(Pw + ((mt) * 16 + g) * 68 + 8 * (nt) + 2 * la3) = lo;       \
        *(float2*)(Pw + ((mt) * 16 + g + 8) * 68 + 8 * (nt) + 2 * la3) = hi;   \
    } while (0)

    for (int t = 0; t < NTILES; t++) {
        if (t < NTILES - 1) cp_wait1(); else cp_wait0();
        __syncthreads();
        if (t + 2 < NTILES) { AT_STAGE(t + 2, (t + 2) % 3); cp_commit(); }

        const float* K1 = sm + (t % 3) * K68W;
        const float* K2 = sm + K72_OFF + (t % 3) * K72W;

        float sacc[2][8][4];
#pragma unroll
        for (int mt = 0; mt < 2; mt++)
#pragma unroll
            for (int nt = 0; nt < 8; nt++)
#pragma unroll
                for (int e = 0; e < 4; e++) sacc[mt][nt][e] = 0.f;

        // Phase 1: GEMM1 on nt 0-3
#pragma unroll
        for (int s = 0; s < 8; s++) {
#pragma unroll
            for (int nt = 0; nt < 4; nt++) {
                uint32_t b0 = __float_as_uint(K1[(8 * nt + g) * 68 + 8 * s + la3]);
                uint32_t b1 = __float_as_uint(K1[(8 * nt + g) * 68 + 8 * s + la3 + 4]);
                mma_tf32(sacc[0][nt], qf[0][s], b0, b1);
                mma_tf32(sacc[1][nt], qf[1][s], b0, b1);
            }
        }
        // Phase 2: GEMM1 on nt 4-7, interleaved with exp of nt 0-3
#pragma unroll
        for (int s = 0; s < 8; s++) {
#pragma unroll
            for (int nt = 4; nt < 8; nt++) {
                uint32_t b0 = __float_as_uint(K1[(8 * nt + g) * 68 + 8 * s + la3]);
                uint32_t b1 = __float_as_uint(K1[(8 * nt + g) * 68 + 8 * s + la3 + 4]);
                mma_tf32(sacc[0][nt], qf[0][s], b0, b1);
                mma_tf32(sacc[1][nt], qf[1][s], b0, b1);
            }
            { // block (mt = s&1, nt = s>>1)
                if ((s & 1) == 0) { EXP_BLOCK(sacc[0][s >> 1], 0, (s >> 1)); }
                else              { EXP_BLOCK(sacc[1][s >> 1], 1, (s >> 1)); }
            }
        }
        __syncwarp();
        // Phase 3: GEMM2 over P cols 0-31 (s2 0-3), interleaved with exp of nt 4-7
#pragma unroll
        for (int sl = 0; sl < 4; sl++) {
            int s2 = sl;
            uint32_t a[2][4];
#pragma unroll
            for (int mt = 0; mt < 2; mt++) {
                int rr = mt * 16 + g;
                a[mt][0] = __float_as_uint(Pw[rr * 68 + 8 * s2 + la3]);
                a[mt][1] = __float_as_uint(Pw[(rr + 8) * 68 + 8 * s2 + la3]);
                a[mt][2] = __float_as_uint(Pw[rr * 68 + 8 * s2 + la3 + 4]);
                a[mt][3] = __float_as_uint(Pw[(rr + 8) * 68 + 8 * s2 + la3 + 4]);
            }
#pragma unroll
            for (int nt = 0; nt < 8; nt++) {
                uint32_t b0 = __float_as_uint(K2[(8 * s2 + la3) * 72 + 8 * nt + g]);
                uint32_t b1 = __float_as_uint(K2[(8 * s2 + la3 + 4) * 72 + 8 * nt + g]);
                mma_tf32(oacc[0][nt], a[0], b0, b1);
                mma_tf32(oacc[1][nt], a[1], b0, b1);
            }
            EXP_BLOCK(sacc[0][4 + sl], 0, (4 + sl));
            EXP_BLOCK(sacc[1][4 + sl], 1, (4 + sl));
        }
        __syncwarp();
        // Phase 4: GEMM2 over P cols 32-63 (s2 4-7)
#pragma unroll
        for (int sl = 0; sl < 4; sl++) {
            int s2 = 4 + sl;
            uint32_t a[2][4];
#pragma unroll
            for (int mt = 0; mt < 2; mt++) {
                int rr = mt * 16 + g;
                a[mt][0] = __float_as_uint(Pw[rr * 68 + 8 * s2 + la3]);
                a[mt][1] = __float_as_uint(Pw[(rr + 8) * 68 + 8 * s2 + la3]);
                a[mt][2] = __float_as_uint(Pw[rr * 68 + 8 * s2 + la3 + 4]);
                a[mt][3] = __float_as_uint(Pw[(rr + 8) * 68 + 8 * s2 + la3 + 4]);
            }
#pragma unroll
            for (int nt = 0; nt < 8; nt++) {
                uint32_t b0 = __float_as_uint(K2[(8 * s2 + la3) * 72 + 8 * nt + g]);
                uint32_t b1 = __float_as_uint(K2[(8 * s2 + la3 + 4) * 72 + 8 * nt + g]);
                mma_tf32(oacc[0][nt], a[0], b0, b1);
                mma_tf32(oacc[1][nt], a[1], b0, b1);
            }
        }
        __syncwarp();
    }

    // ---- Epilogue: scale by sqrt(64)/rowsum, write out ----
#pragma unroll
    for (int mt = 0; mt < 2; mt++) {
        float s0 = psum[mt][0], s1 = psum[mt][1];
        s0 += __shfl_xor_sync(0xffffffffu, s0, 1);
        s0 += __shfl_xor_sync(0xffffffffu, s0, 2);
        s1 += __shfl_xor_sync(0xffffffffu, s1, 1);
        s1 += __shfl_xor_sync(0xffffffffu, s1, 2);
        float sc0 = 8.0f / s0;
        float sc1 = 8.0f / s1;
        int rlo = q0 + wr + mt * 16 + g;
#pragma unroll
        for (int nt = 0; nt < 8; nt++) {
            int col = h * ND + 8 * nt + 2 * la3;
            float2 lo = make_float2(oacc[0][nt][0] * sc0, oacc[0][nt][1] * sc0);
            float2 hi = make_float2(oacc[0][nt][2] * sc1, oacc[0][nt][3] * sc1);
            *(float2*)(Out + (size_t)rlo * OUTF + col) = lo;
            *(float2*)(Out + (size_t)(rlo + 8) * OUTF + col) = hi;
            // mt==1 handled below
            if (mt == 1) {
                lo = make_float2(oacc[1][nt][0] * sc0, oacc[1][nt][1] * sc0);
                hi = make_float2(oacc[1][nt][2] * sc1, oacc[1][nt][3] * sc1);
                *(float2*)(Out + (size_t)rlo * OUTF + col) = lo;
                *(float2*)(Out + (size_t)(rlo + 8) * OUTF + col) = hi;
            } else {
                lo = make_float2(oacc[0][nt][0] * sc0, oacc[0][nt][1] * sc0);
                hi = make_float2(oacc[0][nt][2] * sc1, oacc[0][nt][3] * sc1);
                *(float2*)(Out + (size_t)rlo * OUTF + col) = lo;
                *(float2*)(Out + (size_t)(rlo + 8) * OUTF + col) = hi;
            }
        }
    }
}

// ===========================================================================
extern "C" void kernel_launch(void* const* d_in, const int* in_sizes, int n_in,
                              void* d_out, int out_size) {
    const float* x = (const float*)d_in[0];
    const float* W = (const float*)d_in[1];
    const float* mem = (const float*)d_in[2];
    float* out = (float*)d_out;

    float *qn, *mn;
    cudaGetSymbolAddress((void**)&qn, g_qn);
    cudaGetSymbolAddress((void**)&mn, g_mn);

    cudaFuncSetAttribute(qgemm_mma, cudaFuncAttributeMaxDynamicSharedMemorySize,
                         QG_SMEM);
    cudaFuncSetAttribute(attn_mma, cudaFuncAttributeMaxDynamicSharedMemorySize,
                         AT_SMEM);

    qgemm_mma<<<dim3(OUTF / 128, NB / 128), 256, QG_SMEM>>>(x, W, qn);
    rownorm64_kernel<<<(NH * NM) / 8, 256>>>(mem, mn);
    attn_mma<<<dim3(NB / 256, NH), 256, AT_SMEM>>>(qn, mn, out);
}

// round 6
// speedup vs baseline: 8.1386x; 1.2692x over previous
#include <cuda_runtime.h>
#include <cstdint>

#define NB 4096
#define INF 1024
#define OUTF 1024
#define NH 16
#define NM 4096
#define ND 64

// Scratch (device globals: allocation-free rule)
__device__ float g_qn[NB * OUTF];
__device__ float g_mn[NH * NM * ND];

// ===========================================================================
// helpers
// ===========================================================================
__device__ __forceinline__ uint32_t smem_u32(const void* p) {
    uint32_t a;
    asm("{ .reg .u64 t; cvta.to.shared.u64 t, %1; cvt.u32.u64 %0, t; }"
        : "=r"(a) : "l"(p));
    return a;
}
__device__ __forceinline__ uint32_t f2tf32(float f) {
    uint32_t u;
    asm("cvt.rna.tf32.f32 %0, %1;" : "=r"(u) : "f"(f));
    return u;
}
__device__ __forceinline__ float f2tf32f(float f) {
    return __uint_as_float(f2tf32(f));
}
// pack two floats to fp16x2 (lo -> low half, hi -> high half)
__device__ __forceinline__ uint32_t pack_h2(float lo, float hi) {
    uint32_t r;
    asm("cvt.rn.f16x2.f32 %0, %1, %2;" : "=r"(r) : "f"(hi), "f"(lo));
    return r;
}
__device__ __forceinline__ void mma_tf32(float* d, const uint32_t* a,
                                         uint32_t b0, uint32_t b1) {
    asm volatile(
        "mma.sync.aligned.m16n8k8.row.col.f32.tf32.tf32.f32 "
        "{%0,%1,%2,%3},{%4,%5,%6,%7},{%8,%9},{%0,%1,%2,%3};"
        : "+f"(d[0]), "+f"(d[1]), "+f"(d[2]), "+f"(d[3])
        : "r"(a[0]), "r"(a[1]), "r"(a[2]), "r"(a[3]), "r"(b0), "r"(b1));
}
__device__ __forceinline__ void mma_f16(float* d, uint32_t a0, uint32_t a1,
                                        uint32_t a2, uint32_t a3,
                                        uint32_t b0, uint32_t b1) {
    asm volatile(
        "mma.sync.aligned.m16n8k16.row.col.f32.f16.f16.f32 "
        "{%0,%1,%2,%3},{%4,%5,%6,%7},{%8,%9},{%0,%1,%2,%3};"
        : "+f"(d[0]), "+f"(d[1]), "+f"(d[2]), "+f"(d[3])
        : "r"(a0), "r"(a1), "r"(a2), "r"(a3), "r"(b0), "r"(b1));
}
__device__ __forceinline__ void cpasync16(uint32_t dst, const void* src) {
    asm volatile("cp.async.cg.shared.global [%0], [%1], 16;"
                 :: "r"(dst), "l"(src) : "memory");
}
__device__ __forceinline__ void cp_commit() {
    asm volatile("cp.async.commit_group;" ::: "memory");
}

// ===========================================================================
// q-GEMM: qn = rownorm64(x @ W^T), tf32-rounded output. cp.async 3-stage.
// ===========================================================================
#define QGS 20
#define QG_TILE (128 * QGS)
#define QG_WOFF (3 * QG_TILE)
#define QG_SMEM (6 * QG_TILE * 4)

__global__ __launch_bounds__(256, 2) void qgemm_mma(const float* __restrict__ X,
                                                    const float* __restrict__ W,
                                                    float* __restrict__ Qn) {
    extern __shared__ float qsm[];
    uint32_t smb = smem_u32(qsm);

    int tid = threadIdx.x;
    int lane = tid & 31, w = tid >> 5;
    int g = lane >> 2, la3 = lane & 3;
    int wm = (w & 3) * 32;
    int wn = (w >> 2) * 64;
    int m0 = blockIdx.y * 128, n0 = blockIdx.x * 128;

    float acc[2][8][4];
#pragma unroll
    for (int mt = 0; mt < 2; mt++)
#pragma unroll
        for (int nt = 0; nt < 8; nt++)
#pragma unroll
            for (int e = 0; e < 4; e++) acc[mt][nt][e] = 0.f;

#define QG_STAGE(kt, sl)                                                       \
    do {                                                                       \
        _Pragma("unroll")                                                      \
        for (int u = 0; u < 2; u++) {                                          \
            int chunk = tid + 256 * u;                                         \
            int r = chunk >> 2, c4 = (chunk & 3) << 2;                         \
            cpasync16(smb + (uint32_t)((sl) * QG_TILE + r * QGS + c4) * 4,     \
                      X + (size_t)(m0 + r) * INF + (kt) * 16 + c4);            \
            cpasync16(smb + (uint32_t)(QG_WOFF + (sl) * QG_TILE + r * QGS + c4) * 4, \
                      W + (size_t)(n0 + r) * INF + (kt) * 16 + c4);            \
        }                                                                      \
    } while (0)

    QG_STAGE(0, 0); cp_commit();
    QG_STAGE(1, 1); cp_commit();

    for (int kt = 0; kt < 64; kt++) {
        if (kt < 63) asm volatile("cp.async.wait_group 1;" ::: "memory");
        else         asm volatile("cp.async.wait_group 0;" ::: "memory");
        __syncthreads();
        if (kt + 2 < 64) { QG_STAGE(kt + 2, (kt + 2) % 3); cp_commit(); }

        const float* Xs = qsm + (kt % 3) * QG_TILE;
        const float* Ws = qsm + QG_WOFF + (kt % 3) * QG_TILE;
#pragma unroll
        for (int s = 0; s < 2; s++) {
            uint32_t af[2][4];
#pragma unroll
            for (int mt = 0; mt < 2; mt++) {
                int rr = wm + mt * 16 + g;
                af[mt][0] = f2tf32(Xs[rr * QGS + 8 * s + la3]);
                af[mt][1] = f2tf32(Xs[(rr + 8) * QGS + 8 * s + la3]);
                af[mt][2] = f2tf32(Xs[rr * QGS + 8 * s + la3 + 4]);
                af[mt][3] = f2tf32(Xs[(rr + 8) * QGS + 8 * s + la3 + 4]);
            }
#pragma unroll
            for (int nt = 0; nt < 8; nt++) {
                int nr = wn + nt * 8 + g;
                uint32_t b0 = f2tf32(Ws[nr * QGS + 8 * s + la3]);
                uint32_t b1 = f2tf32(Ws[nr * QGS + 8 * s + la3 + 4]);
                mma_tf32(acc[0][nt], af[0], b0, b1);
                mma_tf32(acc[1][nt], af[1], b0, b1);
            }
        }
    }

    // fused per-head (64-col) L2 norm epilogue; write tf32-rounded qn
#pragma unroll
    for (int mt = 0; mt < 2; mt++) {
        float sq0 = 0.f, sq1 = 0.f;
#pragma unroll
        for (int nt = 0; nt < 8; nt++) {
            sq0 = fmaf(acc[mt][nt][0], acc[mt][nt][0], sq0);
            sq0 = fmaf(acc[mt][nt][1], acc[mt][nt][1], sq0);
            sq1 = fmaf(acc[mt][nt][2], acc[mt][nt][2], sq1);
            sq1 = fmaf(acc[mt][nt][3], acc[mt][nt][3], sq1);
        }
        sq0 += __shfl_xor_sync(0xffffffffu, sq0, 1);
        sq0 += __shfl_xor_sync(0xffffffffu, sq0, 2);
        sq1 += __shfl_xor_sync(0xffffffffu, sq1, 1);
        sq1 += __shfl_xor_sync(0xffffffffu, sq1, 2);
        float r0 = rsqrtf(sq0), r1 = rsqrtf(sq1);
        int rlo = m0 + wm + mt * 16 + g;
#pragma unroll
        for (int nt = 0; nt < 8; nt++) {
            int col = n0 + wn + nt * 8 + 2 * la3;
            float2 lo = make_float2(f2tf32f(acc[mt][nt][0] * r0),
                                    f2tf32f(acc[mt][nt][1] * r0));
            float2 hi = make_float2(f2tf32f(acc[mt][nt][2] * r1),
                                    f2tf32f(acc[mt][nt][3] * r1));
            *(float2*)(Qn + (size_t)rlo * OUTF + col) = lo;
            *(float2*)(Qn + (size_t)(rlo + 8) * OUTF + col) = hi;
        }
    }
}

// ===========================================================================
// Row L2-normalize memories, 64-elem rows, tf32-rounded output
// ===========================================================================
__global__ __launch_bounds__(256) void rownorm64_kernel(const float* __restrict__ src,
                                                        float* __restrict__ dst) {
    int row = blockIdx.x * 8 + (threadIdx.x >> 5);
    int lane = threadIdx.x & 31;
    const float* p = src + (size_t)row * 64 + lane * 2;
    float2 v = *(const float2*)p;
    float ss = fmaf(v.x, v.x, v.y * v.y);
#pragma unroll
    for (int o = 16; o > 0; o >>= 1) ss += __shfl_xor_sync(0xffffffffu, ss, o);
    float r = rsqrtf(ss);
    float2 w;
    w.x = f2tf32f(v.x * r);
    w.y = f2tf32f(v.y * r);
    *(float2*)(dst + (size_t)row * 64 + lane * 2) = w;
}

// ===========================================================================
// Attention. CTA = (head, 256 q rows), 8 warps x 32 rows. KT=64.
// GEMM1 tf32 (K68 smem, 3-stage cp.async). exp via MUFU __expf.
// GEMM2 fp16 m16n8k16: A (=P) packed directly in registers from the GEMM1
// C-fragments (fp16 has tf32's 10 mantissa bits -> precision like R4);
// B (=V) from an fp16 row-pair-packed smem tile built from K68 each tile.
// smem: K68[3][64*68] f32 | Vpk[32*72] u32 | Qstage[256*68] f32
// ===========================================================================
#define KT 64
#define K68W (KT * 68)
#define VPK_OFF (3 * K68W)           /* word offset */
#define QST_OFF (3 * K68W + 32 * 72)
#define AT_SMEM ((3 * K68W + 32 * 72 + 256 * 68) * 4)
#define NTILES (NM / KT)

__global__ __launch_bounds__(256, 1) void attn_mma(const float* __restrict__ Qn,
                                                   const float* __restrict__ Mn,
                                                   float* __restrict__ Out) {
    extern __shared__ float sm[];
    uint32_t smb = smem_u32(sm);
    uint32_t* vpk = (uint32_t*)(sm + VPK_OFF);

    int tid = threadIdx.x;
    int lane = tid & 31, w = tid >> 5;
    int g = lane >> 2, la3 = lane & 3;
    int h = blockIdx.y;
    int q0 = blockIdx.x * 256;
    const float* mh = Mn + (size_t)h * NM * ND;

#define AT_STAGE(tt, sl)                                                       \
    do {                                                                       \
        const float* src_ = mh + (size_t)(tt) * KT * ND;                       \
        _Pragma("unroll")                                                      \
        for (int u = 0; u < 4; u++) {                                          \
            int chunk = tid + 256 * u;                                         \
            int r = chunk >> 4, c4 = (chunk & 15) << 2;                        \
            cpasync16(smb + (uint32_t)((sl) * K68W + r * 68 + c4) * 4,         \
                      src_ + r * ND + c4);                                     \
        }                                                                      \
    } while (0)

    AT_STAGE(0, 0); cp_commit();
    AT_STAGE(1, 1); cp_commit();
    AT_STAGE(2, 2); cp_commit();

    // ---- Stage Q tile (already tf32-rounded) ----
    {
        int row = tid >> 1;
        int c0 = (tid & 1) * 32;
#pragma unroll
        for (int hf = 0; hf < 2; hf++) {
            int r = row + hf * 128;
            const float* qp = Qn + (size_t)(q0 + r) * OUTF + h * ND + c0;
            float* dst = sm + QST_OFF + r * 68 + c0;
#pragma unroll
            for (int u = 0; u < 8; u++)
                *(float4*)(dst + 4 * u) = *(const float4*)(qp + 4 * u);
        }
    }
    __syncthreads();

    // ---- persistent Q a-frags ----
    int wr = w * 32;
    uint32_t qf[2][8][4];
#pragma unroll
    for (int mt = 0; mt < 2; mt++)
#pragma unroll
        for (int s = 0; s < 8; s++) {
            int rr = wr + mt * 16 + g;
            const float* base = sm + QST_OFF;
            qf[mt][s][0] = __float_as_uint(base[rr * 68 + 8 * s + la3]);
            qf[mt][s][1] = __float_as_uint(base[(rr + 8) * 68 + 8 * s + la3]);
            qf[mt][s][2] = __float_as_uint(base[rr * 68 + 8 * s + la3 + 4]);
            qf[mt][s][3] = __float_as_uint(base[(rr + 8) * 68 + 8 * s + la3 + 4]);
        }

    float oacc[2][8][4];
#pragma unroll
    for (int mt = 0; mt < 2; mt++)
#pragma unroll
        for (int nt = 0; nt < 8; nt++)
#pragma unroll
            for (int e = 0; e < 4; e++) oacc[mt][nt][e] = 0.f;
    float psum[2][2] = {{0.f, 0.f}, {0.f, 0.f}};

    int vc = tid & 63;        // Vpack build: column
    int vrpg = tid >> 6;      // row-pair group (0..3)

    for (int t = 0; t < NTILES; t++) {
        // stage t must be complete
        if (t <= NTILES - 3)      asm volatile("cp.async.wait_group 2;" ::: "memory");
        else if (t == NTILES - 2) asm volatile("cp.async.wait_group 1;" ::: "memory");
        else                      asm volatile("cp.async.wait_group 0;" ::: "memory");
        __syncthreads();  // K68(t) visible; all warps done with prev tile

        const float* K1 = sm + (t % 3) * K68W;

        // ---- Build fp16 packed V tile from K68(t) ----
#pragma unroll
        for (int i = 0; i < 8; i++) {
            int rp = vrpg * 8 + i;
            float lo = K1[(2 * rp) * 68 + vc];
            float hi = K1[(2 * rp + 1) * 68 + vc];
            vpk[rp * 72 + vc] = pack_h2(lo, hi);
        }

        // ---- GEMM1: S = Q K^T (tf32) ----
        float sacc[2][8][4];
#pragma unroll
        for (int mt = 0; mt < 2; mt++)
#pragma unroll
            for (int nt = 0; nt < 8; nt++)
#pragma unroll
                for (int e = 0; e < 4; e++) sacc[mt][nt][e] = 0.f;

#pragma unroll
        for (int s = 0; s < 8; s++) {
#pragma unroll
            for (int nt = 0; nt < 8; nt++) {
                uint32_t b0 = __float_as_uint(K1[(8 * nt + g) * 68 + 8 * s + la3]);
                uint32_t b1 = __float_as_uint(K1[(8 * nt + g) * 68 + 8 * s + la3 + 4]);
                mma_tf32(sacc[0][nt], qf[0][s], b0, b1);
                mma_tf32(sacc[1][nt], qf[1][s], b0, b1);
            }
        }

        // ---- exp (MUFU) + row sums + pack P into fp16 a-frags ----
        uint32_t pf[2][8][2];
#pragma unroll
        for (int mt = 0; mt < 2; mt++)
#pragma unroll
            for (int nt = 0; nt < 8; nt++) {
                float e0 = __expf(sacc[mt][nt][0]);
                float e1 = __expf(sacc[mt][nt][1]);
                float e2 = __expf(sacc[mt][nt][2]);
                float e3 = __expf(sacc[mt][nt][3]);
                psum[mt][0] += e0 + e1;
                psum[mt][1] += e2 + e3;
                pf[mt][nt][0] = pack_h2(e0, e1);
                pf[mt][nt][1] = pack_h2(e2, e3);
            }

        __syncthreads();  // Vpack complete before GEMM2 reads it

        // overlap: kick off stage t+3 during GEMM2 (buffer t%3 now free)
        if (t + 3 < NTILES) { AT_STAGE(t + 3, (t + 3) % 3); cp_commit(); }

        // ---- GEMM2: O += P V  (fp16, P from regs) ----
#pragma unroll
        for (int s2 = 0; s2 < 4; s2++) {
#pragma unroll
            for (int nt = 0; nt < 8; nt++) {
                uint32_t b0 = vpk[(8 * s2 + la3) * 72 + 8 * nt + g];
                uint32_t b1 = vpk[(8 * s2 + la3 + 4) * 72 + 8 * nt + g];
                mma_f16(oacc[0][nt],
                        pf[0][2 * s2][0], pf[0][2 * s2][1],
                        pf[0][2 * s2 + 1][0], pf[0][2 * s2 + 1][1], b0, b1);
                mma_f16(oacc[1][nt],
                        pf[1][2 * s2][0], pf[1][2 * s2][1],
                        pf[1][2 * s2 + 1][0], pf[1][2 * s2 + 1][1], b0, b1);
            }
        }
    }

    // ---- Epilogue: scale by sqrt(64)/rowsum, write out ----
#pragma unroll
    for (int mt = 0; mt < 2; mt++) {
        float s0 = psum[mt][0], s1 = psum[mt][1];
        s0 += __shfl_xor_sync(0xffffffffu, s0, 1);
        s0 += __shfl_xor_sync(0xffffffffu, s0, 2);
        s1 += __shfl_xor_sync(0xffffffffu, s1, 1);
        s1 += __shfl_xor_sync(0xffffffffu, s1, 2);
        float sc0 = 8.0f / s0;
        float sc1 = 8.0f / s1;
        int rlo = q0 + wr + mt * 16 + g;
#pragma unroll
        for (int nt = 0; nt < 8; nt++) {
            int col = h * ND + 8 * nt + 2 * la3;
            float2 lo = make_float2(oacc[mt][nt][0] * sc0, oacc[mt][nt][1] * sc0);
            float2 hi = make_float2(oacc[mt][nt][2] * sc1, oacc[mt][nt][3] * sc1);
            *(float2*)(Out + (size_t)rlo * OUTF + col) = lo;
            *(float2*)(Out + (size_t)(rlo + 8) * OUTF + col) = hi;
        }
    }
}

// ===========================================================================
extern "C" void kernel_launch(void* const* d_in, const int* in_sizes, int n_in,
                              void* d_out, int out_size) {
    const float* x = (const float*)d_in[0];
    const float* W = (const float*)d_in[1];
    const float* mem = (const float*)d_in[2];
    float* out = (float*)d_out;

    float *qn, *mn;
    cudaGetSymbolAddress((void**)&qn, g_qn);
    cudaGetSymbolAddress((void**)&mn, g_mn);

    cudaFuncSetAttribute(qgemm_mma, cudaFuncAttributeMaxDynamicSharedMemorySize,
                         QG_SMEM);
    cudaFuncSetAttribute(attn_mma, cudaFuncAttributeMaxDynamicSharedMemorySize,
                         AT_SMEM);

    qgemm_mma<<<dim3(OUTF / 128, NB / 128), 256, QG_SMEM>>>(x, W, qn);
    rownorm64_kernel<<<(NH * NM) / 8, 256>>>(mem, mn);
    attn_mma<<<dim3(NB / 256, NH), 256, AT_SMEM>>>(qn, mn, out);
}

// round 7
// speedup vs baseline: 11.2801x; 1.3860x over previous
#include <cuda_runtime.h>
#include <cstdint>

#define NB 4096
#define INF 1024
#define OUTF 1024
#define NH 16
#define NM 4096
#define ND 64

// Scratch (device globals: allocation-free rule). All fp16-pair packed (u32).
__device__ uint32_t g_xh[NB * INF / 2];
__device__ uint32_t g_wh[OUTF * INF / 2];
__device__ uint32_t g_qh[NB * OUTF / 2];
__device__ uint32_t g_mh[NH * NM * ND / 2];

// ===========================================================================
// helpers
// ===========================================================================
__device__ __forceinline__ uint32_t smem_u32(const void* p) {
    uint32_t a;
    asm("{ .reg .u64 t; cvta.to.shared.u64 t, %1; cvt.u32.u64 %0, t; }"
        : "=r"(a) : "l"(p));
    return a;
}
// pack two floats to fp16x2 (lo -> low half, hi -> high half)
__device__ __forceinline__ uint32_t pack_h2(float lo, float hi) {
    uint32_t r;
    asm("cvt.rn.f16x2.f32 %0, %1, %2;" : "=r"(r) : "f"(hi), "f"(lo));
    return r;
}
__device__ __forceinline__ void mma_f16(float* d, uint32_t a0, uint32_t a1,
                                        uint32_t a2, uint32_t a3,
                                        uint32_t b0, uint32_t b1) {
    asm volatile(
        "mma.sync.aligned.m16n8k16.row.col.f32.f16.f16.f32 "
        "{%0,%1,%2,%3},{%4,%5,%6,%7},{%8,%9},{%0,%1,%2,%3};"
        : "+f"(d[0]), "+f"(d[1]), "+f"(d[2]), "+f"(d[3])
        : "r"(a0), "r"(a1), "r"(a2), "r"(a3), "r"(b0), "r"(b1));
}
__device__ __forceinline__ void cpasync16(uint32_t dst, const void* src) {
    asm volatile("cp.async.cg.shared.global [%0], [%1], 16;"
                 :: "r"(dst), "l"(src) : "memory");
}
__device__ __forceinline__ void cp_commit() {
    asm volatile("cp.async.commit_group;" ::: "memory");
}

// ===========================================================================
// Pack f32 -> fp16 pairs
// ===========================================================================
__global__ __launch_bounds__(256) void cvt_pack(const float4* __restrict__ src,
                                                uint2* __restrict__ dst, int n4) {
    int i = blockIdx.x * 256 + threadIdx.x;
    if (i < n4) {
        float4 v = src[i];
        uint2 o;
        o.x = pack_h2(v.x, v.y);
        o.y = pack_h2(v.z, v.w);
        dst[i] = o;
    }
}

// ===========================================================================
// Row L2-normalize memories, 64-elem rows -> fp16 pairs
// ===========================================================================
__global__ __launch_bounds__(256) void rownorm64_h(const float* __restrict__ src,
                                                   uint32_t* __restrict__ dst) {
    int row = blockIdx.x * 8 + (threadIdx.x >> 5);
    int lane = threadIdx.x & 31;
    float2 v = *(const float2*)(src + (size_t)row * 64 + lane * 2);
    float ss = fmaf(v.x, v.x, v.y * v.y);
#pragma unroll
    for (int o = 16; o > 0; o >>= 1) ss += __shfl_xor_sync(0xffffffffu, ss, o);
    float r = rsqrtf(ss);
    dst[(size_t)row * 32 + lane] = pack_h2(v.x * r, v.y * r);
}

// ===========================================================================
// q-GEMM (fp16): qn = rownorm64(x @ W^T) -> fp16 pairs. 128x128 tile, BK=16,
// 3-stage cp.async, 256 thr, warp tile 32x64, fused per-head L2 norm.
// ===========================================================================
#define QGS 12
#define QG_TILE (128 * QGS)
#define QG_WOFF (3 * QG_TILE)
#define QG_SMEM (6 * QG_TILE * 4)

__global__ __launch_bounds__(256, 2) void qgemm_h(const uint32_t* __restrict__ Xh,
                                                  const uint32_t* __restrict__ Wh,
                                                  uint32_t* __restrict__ Qh) {
    extern __shared__ uint32_t qsm[];
    uint32_t smb = smem_u32(qsm);

    int tid = threadIdx.x;
    int lane = tid & 31, w = tid >> 5;
    int g = lane >> 2, la3 = lane & 3;
    int wm = (w & 3) * 32, wn = (w >> 2) * 64;
    int m0 = blockIdx.y * 128, n0 = blockIdx.x * 128;

    float acc[2][8][4];
#pragma unroll
    for (int mt = 0; mt < 2; mt++)
#pragma unroll
        for (int nt = 0; nt < 8; nt++)
#pragma unroll
            for (int e = 0; e < 4; e++) acc[mt][nt][e] = 0.f;

    int sr = tid >> 1, sc = (tid & 1) * 4;
#define QGH_STAGE(kt, sl)                                                      \
    do {                                                                       \
        cpasync16(smb + (uint32_t)((sl) * QG_TILE + sr * QGS + sc) * 4,        \
                  Xh + (size_t)(m0 + sr) * (INF / 2) + (kt) * 8 + sc);         \
        cpasync16(smb + (uint32_t)(QG_WOFF + (sl) * QG_TILE + sr * QGS + sc) * 4, \
                  Wh + (size_t)(n0 + sr) * (INF / 2) + (kt) * 8 + sc);         \
    } while (0)

    QGH_STAGE(0, 0); cp_commit();
    QGH_STAGE(1, 1); cp_commit();

    for (int kt = 0; kt < 64; kt++) {
        if (kt < 63) asm volatile("cp.async.wait_group 1;" ::: "memory");
        else         asm volatile("cp.async.wait_group 0;" ::: "memory");
        __syncthreads();
        if (kt + 2 < 64) { QGH_STAGE(kt + 2, (kt + 2) % 3); cp_commit(); }

        const uint32_t* Xs = qsm + (kt % 3) * QG_TILE;
        const uint32_t* Ws = qsm + QG_WOFF + (kt % 3) * QG_TILE;

        uint32_t af[2][4];
#pragma unroll
        for (int mt = 0; mt < 2; mt++) {
            int rr = wm + mt * 16 + g;
            af[mt][0] = Xs[rr * QGS + la3];
            af[mt][1] = Xs[(rr + 8) * QGS + la3];
            af[mt][2] = Xs[rr * QGS + la3 + 4];
            af[mt][3] = Xs[(rr + 8) * QGS + la3 + 4];
        }
#pragma unroll
        for (int nt = 0; nt < 8; nt++) {
            int nr = wn + nt * 8 + g;
            uint32_t b0 = Ws[nr * QGS + la3];
            uint32_t b1 = Ws[nr * QGS + la3 + 4];
            mma_f16(acc[0][nt], af[0][0], af[0][1], af[0][2], af[0][3], b0, b1);
            mma_f16(acc[1][nt], af[1][0], af[1][1], af[1][2], af[1][3], b0, b1);
        }
    }

    // fused per-head (64-col) L2 norm epilogue; write fp16 pairs
#pragma unroll
    for (int mt = 0; mt < 2; mt++) {
        float sq0 = 0.f, sq1 = 0.f;
#pragma unroll
        for (int nt = 0; nt < 8; nt++) {
            sq0 = fmaf(acc[mt][nt][0], acc[mt][nt][0], sq0);
            sq0 = fmaf(acc[mt][nt][1], acc[mt][nt][1], sq0);
            sq1 = fmaf(acc[mt][nt][2], acc[mt][nt][2], sq1);
            sq1 = fmaf(acc[mt][nt][3], acc[mt][nt][3], sq1);
        }
        sq0 += __shfl_xor_sync(0xffffffffu, sq0, 1);
        sq0 += __shfl_xor_sync(0xffffffffu, sq0, 2);
        sq1 += __shfl_xor_sync(0xffffffffu, sq1, 1);
        sq1 += __shfl_xor_sync(0xffffffffu, sq1, 2);
        float r0 = rsqrtf(sq0), r1 = rsqrtf(sq1);
        int rlo = m0 + wm + mt * 16 + g;
#pragma unroll
        for (int nt = 0; nt < 8; nt++) {
            int colw = (n0 + wn + nt * 8) / 2 + la3;
            Qh[(size_t)rlo * (OUTF / 2) + colw] =
                pack_h2(acc[mt][nt][0] * r0, acc[mt][nt][1] * r0);
            Qh[(size_t)(rlo + 8) * (OUTF / 2) + colw] =
                pack_h2(acc[mt][nt][2] * r1, acc[mt][nt][3] * r1);
        }
    }
}

// ===========================================================================
// Attention, all fp16. CTA = (head, 256 q rows), 8 warps x 32 rows. KT=64.
// K tiles fp16 d-pair packed (stride 36 words), 3-stage cp.async.
// GEMM1 f16 k16 (Q a-frags persistent in regs). exp via MUFU __expf.
// GEMM2 f16 k16: P straight from C-frags; V j-pair packed (vpk, stride 72)
// built from the K tile with prmt.
// smem (u32 words): K[3][64*36] | vpk[32*72] | Qstage[256*36]  (73.7 KB)
// ===========================================================================
#define KS 36
#define KTW (64 * KS)
#define VPK_OFF (3 * KTW)
#define VPS 72
#define QST_OFF (VPK_OFF + 32 * VPS)
#define QS 36
#define AT_SMEM ((QST_OFF + 256 * QS) * 4)
#define NTILES (NM / 64)

__global__ __launch_bounds__(256, 1) void attn_h(const uint32_t* __restrict__ Qh,
                                                 const uint32_t* __restrict__ Mh,
                                                 float* __restrict__ Out) {
    extern __shared__ uint32_t smu[];
    uint32_t smb = smem_u32(smu);

    int tid = threadIdx.x;
    int lane = tid & 31, w = tid >> 5;
    int g = lane >> 2, la3 = lane & 3;
    int h = blockIdx.y;
    int q0 = blockIdx.x * 256;
    const uint32_t* mhw = Mh + (size_t)h * NM * (ND / 2);

    // ---- Q stage (cp.async group 0) ----
    {
        const uint32_t* qp = Qh + (size_t)(q0 + tid) * (OUTF / 2) + h * 32;
#pragma unroll
        for (int u = 0; u < 8; u++)
            cpasync16(smb + (uint32_t)(QST_OFF + tid * QS + u * 4) * 4, qp + u * 4);
        cp_commit();
    }

#define ATH_STAGE(tt, sl)                                                      \
    do {                                                                       \
        _Pragma("unroll")                                                      \
        for (int u = 0; u < 2; u++) {                                          \
            int chunk = tid + 256 * u;                                         \
            int r = chunk >> 3, cq = (chunk & 7) * 4;                          \
            cpasync16(smb + (uint32_t)((sl) * KTW + r * KS + cq) * 4,          \
                      mhw + (size_t)((tt) * 64 + r) * 32 + cq);                \
        }                                                                      \
    } while (0)

    ATH_STAGE(0, 0); cp_commit();
    ATH_STAGE(1, 1); cp_commit();
    ATH_STAGE(2, 2); cp_commit();

    asm volatile("cp.async.wait_group 2;" ::: "memory");  // Q (+K0) complete
    __syncthreads();

    // ---- persistent Q a-frags (fp16: 4 k16 slices) ----
    int wr = w * 32;
    uint32_t qf[2][4][4];
    {
        const uint32_t* qb = smu + QST_OFF;
#pragma unroll
        for (int mt = 0; mt < 2; mt++)
#pragma unroll
            for (int s = 0; s < 4; s++) {
                int rr = wr + mt * 16 + g;
                qf[mt][s][0] = qb[rr * QS + 8 * s + la3];
                qf[mt][s][1] = qb[(rr + 8) * QS + 8 * s + la3];
                qf[mt][s][2] = qb[rr * QS + 8 * s + la3 + 4];
                qf[mt][s][3] = qb[(rr + 8) * QS + 8 * s + la3 + 4];
            }
    }

    float oacc[2][8][4];
#pragma unroll
    for (int mt = 0; mt < 2; mt++)
#pragma unroll
        for (int nt = 0; nt < 8; nt++)
#pragma unroll
            for (int e = 0; e < 4; e++) oacc[mt][nt][e] = 0.f;
    float psum[2][2] = {{0.f, 0.f}, {0.f, 0.f}};

    uint32_t* vpk = smu + VPK_OFF;
    int brp = tid >> 3;       // vpk build: j-pair row 0..31
    int bcw = tid & 7;        // base packed-col

    for (int t = 0; t < NTILES; t++) {
        if (t <= NTILES - 3)      asm volatile("cp.async.wait_group 2;" ::: "memory");
        else if (t == NTILES - 2) asm volatile("cp.async.wait_group 1;" ::: "memory");
        else                      asm volatile("cp.async.wait_group 0;" ::: "memory");
        __syncthreads();  // K(t) visible; all warps done with vpk(t-1)

        const uint32_t* K1 = smu + (t % 3) * KTW;

        // ---- Build j-pair packed V tile from K tile (prmt transpose) ----
#pragma unroll
        for (int u = 0; u < 4; u++) {
            int cw = bcw + 8 * u;
            uint32_t w0 = K1[(2 * brp) * KS + cw];
            uint32_t w1 = K1[(2 * brp + 1) * KS + cw];
            uint32_t lo, hi;
            asm("prmt.b32 %0, %1, %2, 0x5410;" : "=r"(lo) : "r"(w0), "r"(w1));
            asm("prmt.b32 %0, %1, %2, 0x7632;" : "=r"(hi) : "r"(w0), "r"(w1));
            vpk[brp * VPS + 2 * cw] = lo;
            vpk[brp * VPS + 2 * cw + 1] = hi;
        }

        // ---- GEMM1: S = Q K^T (f16 k16) ----
        float sacc[2][8][4];
#pragma unroll
        for (int mt = 0; mt < 2; mt++)
#pragma unroll
            for (int nt = 0; nt < 8; nt++)
#pragma unroll
                for (int e = 0; e < 4; e++) sacc[mt][nt][e] = 0.f;

#pragma unroll
        for (int s = 0; s < 4; s++) {
#pragma unroll
            for (int nt = 0; nt < 8; nt++) {
                uint32_t b0 = K1[(8 * nt + g) * KS + 8 * s + la3];
                uint32_t b1 = K1[(8 * nt + g) * KS + 8 * s + la3 + 4];
                mma_f16(sacc[0][nt], qf[0][s][0], qf[0][s][1], qf[0][s][2],
                        qf[0][s][3], b0, b1);
                mma_f16(sacc[1][nt], qf[1][s][0], qf[1][s][1], qf[1][s][2],
                        qf[1][s][3], b0, b1);
            }
        }

        // ---- exp (MUFU) + row sums + pack P into fp16 a-frags ----
        uint32_t pf[2][8][2];
#pragma unroll
        for (int mt = 0; mt < 2; mt++)
#pragma unroll
            for (int nt = 0; nt < 8; nt++) {
                float e0 = __expf(sacc[mt][nt][0]);
                float e1 = __expf(sacc[mt][nt][1]);
                float e2 = __expf(sacc[mt][nt][2]);
                float e3 = __expf(sacc[mt][nt][3]);
                psum[mt][0] += e0 + e1;
                psum[mt][1] += e2 + e3;
                pf[mt][nt][0] = pack_h2(e0, e1);
                pf[mt][nt][1] = pack_h2(e2, e3);
            }

        __syncthreads();  // vpk complete before GEMM2 reads it

        // stage t+3 (buffer t%3 free: GEMM1 + vpk build done in all warps)
        if (t + 3 < NTILES) { ATH_STAGE(t + 3, (t + 3) % 3); cp_commit(); }

        // ---- GEMM2: O += P V  (f16, P from regs) ----
#pragma unroll
        for (int s2 = 0; s2 < 4; s2++) {
#pragma unroll
            for (int nt = 0; nt < 8; nt++) {
                uint32_t b0 = vpk[(8 * s2 + la3) * VPS + 8 * nt + g];
                uint32_t b1 = vpk[(8 * s2 + la3 + 4) * VPS + 8 * nt + g];
                mma_f16(oacc[0][nt],
                        pf[0][2 * s2][0], pf[0][2 * s2][1],
                        pf[0][2 * s2 + 1][0], pf[0][2 * s2 + 1][1], b0, b1);
                mma_f16(oacc[1][nt],
                        pf[1][2 * s2][0], pf[1][2 * s2][1],
                        pf[1][2 * s2 + 1][0], pf[1][2 * s2 + 1][1], b0, b1);
            }
        }
    }

    // ---- Epilogue: scale by sqrt(64)/rowsum, write out f32 ----
#pragma unroll
    for (int mt = 0; mt < 2; mt++) {
        float s0 = psum[mt][0], s1 = psum[mt][1];
        s0 += __shfl_xor_sync(0xffffffffu, s0, 1);
        s0 += __shfl_xor_sync(0xffffffffu, s0, 2);
        s1 += __shfl_xor_sync(0xffffffffu, s1, 1);
        s1 += __shfl_xor_sync(0xffffffffu, s1, 2);
        float sc0 = 8.0f / s0;
        float sc1 = 8.0f / s1;
        int rlo = q0 + wr + mt * 16 + g;
#pragma unroll
        for (int nt = 0; nt < 8; nt++) {
            int col = h * ND + 8 * nt + 2 * la3;
            float2 lo = make_float2(oacc[mt][nt][0] * sc0, oacc[mt][nt][1] * sc0);
            float2 hi = make_float2(oacc[mt][nt][2] * sc1, oacc[mt][nt][3] * sc1);
            *(float2*)(Out + (size_t)rlo * OUTF + col) = lo;
            *(float2*)(Out + (size_t)(rlo + 8) * OUTF + col) = hi;
        }
    }
}

// ===========================================================================
extern "C" void kernel_launch(void* const* d_in, const int* in_sizes, int n_in,
                              void* d_out, int out_size) {
    const float* x = (const float*)d_in[0];
    const float* W = (const float*)d_in[1];
    const float* mem = (const float*)d_in[2];
    float* out = (float*)d_out;

    uint32_t *xh, *wh, *qh, *mh;
    cudaGetSymbolAddress((void**)&xh, g_xh);
    cudaGetSymbolAddress((void**)&wh, g_wh);
    cudaGetSymbolAddress((void**)&qh, g_qh);
    cudaGetSymbolAddress((void**)&mh, g_mh);

    cudaFuncSetAttribute(qgemm_h, cudaFuncAttributeMaxDynamicSharedMemorySize,
                         QG_SMEM);
    cudaFuncSetAttribute(attn_h, cudaFuncAttributeMaxDynamicSharedMemorySize,
                         AT_SMEM);

    cvt_pack<<<(NB * INF / 4) / 256, 256>>>((const float4*)x, (uint2*)xh,
                                            NB * INF / 4);
    cvt_pack<<<(OUTF * INF / 4) / 256, 256>>>((const float4*)W, (uint2*)wh,
                                              OUTF * INF / 4);
    rownorm64_h<<<(NH * NM) / 8, 256>>>(mem, mh);
    qgemm_h<<<dim3(OUTF / 128, NB / 128), 256, QG_SMEM>>>(xh, wh, qh);
    attn_h<<<dim3(NB / 256, NH), 256, AT_SMEM>>>(qh, mh, out);
}